// round 3
// baseline (speedup 1.0000x reference)
#include <cuda_runtime.h>

// SrbQpCtrl: reference collapses to tau = zeros([2e6, 10], f32) = 80 MB fill.
// Evidence (R2 ncu): both memset and STG.E.128 fill land at ~3090 B/cyc =
// ~52% of the 6300 B/cyc LTS read cap -> LTS WRITE cap is the HW floor.
// This version: exact-cover, 64 B per thread (4x STG.E.128 back-to-back per
// warp -> 2 KB contiguous per warp), minimal index math, single wave-balanced
// grid. Goal: shave issue/loop overhead and confirm the write-cap floor.

__global__ void __launch_bounds__(256) zero_fill_x4(float4* __restrict__ out, int n4) {
    // Each thread writes 4 consecutive float4 = 64 B.
    int base = (blockIdx.x * blockDim.x + threadIdx.x) * 4;
    const float4 z = make_float4(0.f, 0.f, 0.f, 0.f);
    if (base + 3 < n4) {
        out[base + 0] = z;
        out[base + 1] = z;
        out[base + 2] = z;
        out[base + 3] = z;
    } else {
        for (int i = base; i < n4; ++i) out[i] = z;
    }
}

extern "C" void kernel_launch(void* const* d_in, const int* in_sizes, int n_in,
                              void* d_out, int out_size) {
    (void)d_in; (void)in_sizes; (void)n_in;
    int n4 = out_size / 4;                    // 5,000,000 float4
    const int threads = 256;
    int per_block = threads * 4;              // 1024 float4 per block
    int blocks = (n4 + per_block - 1) / per_block;  // 4883 blocks
    zero_fill_x4<<<blocks, threads>>>((float4*)d_out, n4);

    int tail = out_size - n4 * 4;             // 0 for 20M, defensive only
    if (tail > 0)
        cudaMemsetAsync((float*)d_out + n4 * 4, 0, (size_t)tail * sizeof(float), 0);
}

// round 4
// speedup vs baseline: 1.4848x; 1.4848x over previous
#include <cuda_runtime.h>
#include <cstdint>

// SrbQpCtrl: tau = zeros([2e6,10], f32) = 80,000,000 B constant fill.
// R2/R3 evidence: SIMT STG.E.128 and memset both cap at ~6.2 TB/s (~52% of
// the 6300 B/cyc LTS cap). Test the remaining theory: is the L2 write limit
// per-REQUEST rather than per-byte? TMA bulk S2G stores present full-line
// bulk transactions with ~1000x fewer instructions.

static constexpr int CHUNK = 16000;           // 16-byte multiple; 5000*16000 = 80e6 exactly
static constexpr int SMEM_BYTES = CHUNK;

__global__ void __launch_bounds__(128) bulk_zero(char* __restrict__ out, int n_chunks) {
    __shared__ alignas(128) char buf[SMEM_BYTES];

    // Zero the smem staging buffer (source of every bulk store).
    const float4 z = make_float4(0.f, 0.f, 0.f, 0.f);
    for (int i = threadIdx.x; i < SMEM_BYTES / 16; i += blockDim.x)
        reinterpret_cast<float4*>(buf)[i] = z;
    __syncthreads();
    // Order the generic-proxy smem writes before async-proxy reads.
    asm volatile("fence.proxy.async.shared::cta;" ::: "memory");

    if (threadIdx.x == 0) {
        uint32_t saddr;
        asm("{ .reg .u64 t; cvta.to.shared.u64 t, %1; cvt.u32.u64 %0, t; }"
            : "=r"(saddr) : "l"(buf));
        for (int c = blockIdx.x; c < n_chunks; c += gridDim.x) {
            char* dst = out + (size_t)c * CHUNK;
            asm volatile(
                "cp.async.bulk.global.shared::cta.bulk_group [%0], [%1], %2;"
                :: "l"(dst), "r"(saddr), "n"(CHUNK) : "memory");
        }
        asm volatile("cp.async.bulk.commit_group;" ::: "memory");
        asm volatile("cp.async.bulk.wait_group 0;" ::: "memory");
    }
}

extern "C" void kernel_launch(void* const* d_in, const int* in_sizes, int n_in,
                              void* d_out, int out_size) {
    (void)d_in; (void)in_sizes; (void)n_in;
    size_t total_bytes = (size_t)out_size * sizeof(float);   // 80,000,000
    int n_chunks = (int)(total_bytes / CHUNK);               // 5000
    size_t tail = total_bytes - (size_t)n_chunks * CHUNK;    // 0 for this shape

    const int blocks = 148 * 8;   // 1184: ~4.2 chunks per block, grid-stride balanced
    bulk_zero<<<blocks, 128>>>((char*)d_out, n_chunks);

    if (tail > 0)   // defensive; no-op for 20M floats
        cudaMemsetAsync((char*)d_out + (size_t)n_chunks * CHUNK, 0, tail, 0);
}

// round 5
// speedup vs baseline: 1.7043x; 1.1478x over previous
#include <cuda_runtime.h>

// SrbQpCtrl: tau = zeros([2e6,10], f32) = 80 MB constant fill.
// Established (R1-R4): CE memset, SIMT STG.E.128, and TMA bulk-store all cap
// at ~3100 B/cyc = half the LTS read cap -> chip-level L2 WRITE port floor.
// Floor: ~12.9 us kernel + ~2 us graph overhead. This variant: exact-cover,
// loop-free, two fully-coalesced STG.E.128 per thread (block covers 512
// contiguous float4), minimal issue overhead.

__global__ void __launch_bounds__(256) zero_fill_exact(float4* __restrict__ out, int n4) {
    int base = blockIdx.x * 512 + threadIdx.x;   // block covers [blk*512, blk*512+512)
    const float4 z = make_float4(0.f, 0.f, 0.f, 0.f);
    if (base < n4)        out[base] = z;         // stores 0..255 of the block span
    if (base + 256 < n4)  out[base + 256] = z;   // stores 256..511
}

extern "C" void kernel_launch(void* const* d_in, const int* in_sizes, int n_in,
                              void* d_out, int out_size) {
    (void)d_in; (void)in_sizes; (void)n_in;
    int n4 = out_size / 4;                       // 5,000,000 float4
    int blocks = (n4 + 511) / 512;               // 9766 blocks, exact cover
    zero_fill_exact<<<blocks, 256>>>((float4*)d_out, n4);

    int tail = out_size - n4 * 4;                // 0 for 20M floats; defensive
    if (tail > 0)
        cudaMemsetAsync((float*)d_out + (size_t)n4 * 4, 0, (size_t)tail * sizeof(float), 0);
}